// round 6
// baseline (speedup 1.0000x reference)
#include <cuda_runtime.h>
#include <cuda_bf16.h>
#include <cuda_fp16.h>
#include <cstdint>

#define N_NODES 100000
#define N_EDGES 3200000
#define TOT_E   (N_EDGES + N_NODES)
#define IN_F    512
#define HID     128
#define TILE_M  128
#define KC      32
#define NCHUNK  (IN_F / KC)     // 16
#define NBLK_SCAN 98

#define A_LD 40
#define W_LD 136
#define ABUF (TILE_M * A_LD)          // 5120 elems
#define WBUF (KC * W_LD)              // 4352 elems
#define BUFE (2 * ABUF + 2 * WBUF)    // 18944 elems per buffer
#define S_BYTES (2 * BUFE * 2)        // 75776 bytes

// ---------------- scratch ----------------
__device__ __align__(16) __half g_xh[(size_t)N_NODES * HID];   // fp16 feature cache
__device__ float g_asrc[N_NODES];
__device__ float g_adst[N_NODES];
__device__ int   g_deg[N_NODES];
__device__ int   g_off[N_NODES + 1];
__device__ int   g_cur[N_NODES];
__device__ int   g_ssrc[TOT_E];
__device__ float g_sexp[TOT_E];
__device__ int   g_is64;
__device__ __align__(16) __nv_bfloat16 g_wbh[IN_F * HID];  // W hi [k][n]
__device__ __align__(16) __nv_bfloat16 g_wbl[IN_F * HID];  // W lo [k][n]
__device__ int   g_part[128];

// ---------------- helpers ----------------
__device__ __forceinline__ uint32_t smem_u32(const void* p) {
    uint32_t a;
    asm("{ .reg .u64 t; cvta.to.shared.u64 t, %1; cvt.u32.u64 %0, t; }" : "=r"(a) : "l"(p));
    return a;
}
__device__ __forceinline__ void ldsm4(uint32_t* r, uint32_t addr) {
    asm volatile("ldmatrix.sync.aligned.m8n8.x4.shared.b16 {%0,%1,%2,%3}, [%4];"
                 : "=r"(r[0]), "=r"(r[1]), "=r"(r[2]), "=r"(r[3]) : "r"(addr));
}
__device__ __forceinline__ void ldsm4t(uint32_t* r, uint32_t addr) {
    asm volatile("ldmatrix.sync.aligned.m8n8.x4.trans.shared.b16 {%0,%1,%2,%3}, [%4];"
                 : "=r"(r[0]), "=r"(r[1]), "=r"(r[2]), "=r"(r[3]) : "r"(addr));
}
__device__ __forceinline__ void mma16816(float* c, const uint32_t* a, const uint32_t* b) {
    asm volatile("mma.sync.aligned.m16n8k16.row.col.f32.bf16.bf16.f32 "
                 "{%0,%1,%2,%3}, {%4,%5,%6,%7}, {%8,%9}, {%0,%1,%2,%3};"
                 : "+f"(c[0]), "+f"(c[1]), "+f"(c[2]), "+f"(c[3])
                 : "r"(a[0]), "r"(a[1]), "r"(a[2]), "r"(a[3]), "r"(b[0]), "r"(b[1]));
}

// ---------------- adj helpers ----------------
__device__ __forceinline__ int load_adj(const void* adj, long long i, int is64) {
    if (is64) return (int)((const long long*)adj)[i];
    return ((const int*)adj)[i];
}
__global__ void detect_kernel(const void* adj) {
    const int* p = (const int*)adj;
    int acc = 0;
#pragma unroll
    for (int k = 0; k < 64; k++) acc |= p[2 * k + 1];
    for (int k = 0; k < 64; k++) acc |= p[2 * (k * 9973 + 1000) + 1];
    g_is64 = (acc == 0) ? 1 : 0;
}
__global__ void zero_kernel() {
    int i = blockIdx.x * blockDim.x + threadIdx.x;
    if (i < N_NODES) g_deg[i] = 0;
}

// ---------------- W split prep ----------------
__global__ void wprep_kernel(const float* __restrict__ W) {
    int i = blockIdx.x * blockDim.x + threadIdx.x;
    if (i >= IN_F * HID) return;
    float v = W[i];
    __nv_bfloat16 h = __float2bfloat16(v);
    float r = v - __bfloat162float(h);
    g_wbh[i] = h;
    g_wbl[i] = __float2bfloat16(r);
}

// ---------------- pipelined HMMA GEMM (3-term bf16 split) ----------------
__global__ void __launch_bounds__(256) gemm_kernel(const float* __restrict__ A,
                                                   const float* __restrict__ attsrc,
                                                   const float* __restrict__ attdst) {
    extern __shared__ __nv_bfloat16 sm[];
    const int tid = threadIdx.x, lane = tid & 31, wid = tid >> 5;
    const int row0 = blockIdx.x * TILE_M;
    const int warp_m = wid & 3, warp_n = wid >> 2;

    float acc[16][4];
#pragma unroll
    for (int t = 0; t < 16; t++)
#pragma unroll
        for (int j = 0; j < 4; j++) acc[t][j] = 0.f;

    const int ar = tid >> 1, ah_ = tid & 1;
    const int agr = row0 + ar;
    const int wk = tid >> 3, wn0 = (tid & 7) * 16;

    float f[16];
    uint4 vh0, vh1, vl0, vl1;

    // ---- register load of chunk c ----
#define LOAD_REGS(c) do {                                                       \
        const int k0 = (c) * KC;                                                \
        if (agr < N_NODES) {                                                    \
            const float4* src = (const float4*)&A[(size_t)agr * IN_F + k0 + ah_ * 16]; \
            _Pragma("unroll")                                                   \
            for (int q = 0; q < 4; q++) {                                       \
                float4 v = src[q];                                              \
                f[4*q+0] = v.x; f[4*q+1] = v.y; f[4*q+2] = v.z; f[4*q+3] = v.w; \
            }                                                                   \
        } else {                                                                \
            _Pragma("unroll")                                                   \
            for (int q = 0; q < 16; q++) f[q] = 0.f;                            \
        }                                                                       \
        const uint4* sh = (const uint4*)&g_wbh[(size_t)(k0 + wk) * HID + wn0];  \
        const uint4* sl = (const uint4*)&g_wbl[(size_t)(k0 + wk) * HID + wn0];  \
        vh0 = sh[0]; vh1 = sh[1]; vl0 = sl[0]; vl1 = sl[1];                     \
    } while (0)

    // ---- convert + store regs into buffer b ----
#define STORE_SMEM(b) do {                                                      \
        __nv_bfloat16* dAh = sm + (b) * BUFE;                                   \
        __nv_bfloat16* dAl = dAh + ABUF;                                        \
        __nv_bfloat16* dWh = dAl + ABUF;                                        \
        __nv_bfloat16* dWl = dWh + WBUF;                                        \
        uint32_t h[8], l[8];                                                    \
        _Pragma("unroll")                                                       \
        for (int j = 0; j < 8; j++) {                                           \
            float a = f[2*j], bb = f[2*j+1];                                    \
            __nv_bfloat162 hp = __floats2bfloat162_rn(a, bb);                   \
            float ra = a - __low2float(hp);                                     \
            float rb = bb - __high2float(hp);                                   \
            __nv_bfloat162 lp = __floats2bfloat162_rn(ra, rb);                  \
            h[j] = *reinterpret_cast<uint32_t*>(&hp);                           \
            l[j] = *reinterpret_cast<uint32_t*>(&lp);                           \
        }                                                                       \
        __nv_bfloat16* ph = &dAh[ar * A_LD + ah_ * 16];                         \
        __nv_bfloat16* pl = &dAl[ar * A_LD + ah_ * 16];                         \
        *(uint4*)(ph)     = make_uint4(h[0], h[1], h[2], h[3]);                 \
        *(uint4*)(ph + 8) = make_uint4(h[4], h[5], h[6], h[7]);                 \
        *(uint4*)(pl)     = make_uint4(l[0], l[1], l[2], l[3]);                 \
        *(uint4*)(pl + 8) = make_uint4(l[4], l[5], l[6], l[7]);                 \
        __nv_bfloat16* qh = &dWh[wk * W_LD + wn0];                              \
        __nv_bfloat16* ql = &dWl[wk * W_LD + wn0];                              \
        *(uint4*)(qh) = vh0; *(uint4*)(qh + 8) = vh1;                           \
        *(uint4*)(ql) = vl0; *(uint4*)(ql + 8) = vl1;                           \
    } while (0)

    LOAD_REGS(0);
    STORE_SMEM(0);
    __syncthreads();

    for (int c = 0; c < NCHUNK; c++) {
        const int buf = c & 1;
        if (c < NCHUNK - 1) LOAD_REGS(c + 1);      // LDGs in flight during MMA

        const __nv_bfloat16* Ah = sm + buf * BUFE;
        const __nv_bfloat16* Al = Ah + ABUF;
        const __nv_bfloat16* Wh = Al + ABUF;
        const __nv_bfloat16* Wl = Wh + WBUF;

#pragma unroll
        for (int ks = 0; ks < 2; ks++) {
            uint32_t a_h[2][4], a_l[2][4];
#pragma unroll
            for (int mi = 0; mi < 2; mi++) {
                uint32_t aoff = (warp_m * 32 + mi * 16 + (lane & 15)) * A_LD
                              + ks * 16 + (lane >> 4) * 8;
                ldsm4(a_h[mi], smem_u32(&Ah[aoff]));
                ldsm4(a_l[mi], smem_u32(&Al[aoff]));
            }
#pragma unroll
            for (int nt = 0; nt < 4; nt++) {
                uint32_t b_h[4], b_l[4];
                uint32_t woff = (ks * 16 + (lane & 15)) * W_LD
                              + warp_n * 64 + nt * 16 + (lane >> 4) * 8;
                ldsm4t(b_h, smem_u32(&Wh[woff]));
                ldsm4t(b_l, smem_u32(&Wl[woff]));
#pragma unroll
                for (int mi = 0; mi < 2; mi++) {
                    int t = mi * 8 + nt * 2;
                    mma16816(acc[t],     a_h[mi], b_h);
                    mma16816(acc[t + 1], a_h[mi], b_h + 2);
                    mma16816(acc[t],     a_l[mi], b_h);
                    mma16816(acc[t + 1], a_l[mi], b_h + 2);
                    mma16816(acc[t],     a_h[mi], b_l);
                    mma16816(acc[t + 1], a_h[mi], b_l + 2);
                }
            }
        }
        if (c < NCHUNK - 1) STORE_SMEM(buf ^ 1);
        __syncthreads();
    }

    // ---- epilogue: fp16 g_xh + fused attention dots ----
    float sd[2][2] = {{0.f, 0.f}, {0.f, 0.f}};
    float dd[2][2] = {{0.f, 0.f}, {0.f, 0.f}};
#pragma unroll
    for (int mi = 0; mi < 2; mi++) {
        const int rlo = row0 + warp_m * 32 + mi * 16 + (lane >> 2);
        const int rhi = rlo + 8;
#pragma unroll
        for (int nt = 0; nt < 4; nt++) {
#pragma unroll
            for (int h = 0; h < 2; h++) {
                int t = mi * 8 + nt * 2 + h;
                int col = warp_n * 64 + nt * 16 + h * 8 + (lane & 3) * 2;
                float as0 = __ldg(&attsrc[col]), as1 = __ldg(&attsrc[col + 1]);
                float ad0 = __ldg(&attdst[col]), ad1 = __ldg(&attdst[col + 1]);
                float2 v0 = make_float2(acc[t][0], acc[t][1]);
                float2 v1 = make_float2(acc[t][2], acc[t][3]);
                sd[mi][0] += v0.x * as0 + v0.y * as1;
                dd[mi][0] += v0.x * ad0 + v0.y * ad1;
                sd[mi][1] += v1.x * as0 + v1.y * as1;
                dd[mi][1] += v1.x * ad0 + v1.y * ad1;
                if (rlo < N_NODES) {
                    __half2 p = __float22half2_rn(v0);
                    *(uint32_t*)&g_xh[(size_t)rlo * HID + col] = *(uint32_t*)&p;
                }
                if (rhi < N_NODES) {
                    __half2 p = __float22half2_rn(v1);
                    *(uint32_t*)&g_xh[(size_t)rhi * HID + col] = *(uint32_t*)&p;
                }
            }
        }
    }
#pragma unroll
    for (int o = 1; o <= 2; o <<= 1) {
#pragma unroll
        for (int mi = 0; mi < 2; mi++)
#pragma unroll
            for (int h = 0; h < 2; h++) {
                sd[mi][h] += __shfl_xor_sync(0xffffffffu, sd[mi][h], o);
                dd[mi][h] += __shfl_xor_sync(0xffffffffu, dd[mi][h], o);
            }
    }
    // combine the two warp_n halves through smem
    float* sdp = (float*)sm;          // [128][2]
    float* ddp = sdp + 256;           // [128][2]
    if ((lane & 3) == 0) {
#pragma unroll
        for (int mi = 0; mi < 2; mi++)
#pragma unroll
            for (int h = 0; h < 2; h++) {
                int rt = warp_m * 32 + mi * 16 + (lane >> 2) + h * 8;
                sdp[rt * 2 + warp_n] = sd[mi][h];
                ddp[rt * 2 + warp_n] = dd[mi][h];
            }
    }
    __syncthreads();
    if (tid < 128) {
        int gr = row0 + tid;
        if (gr < N_NODES) {
            g_asrc[gr] = sdp[tid * 2] + sdp[tid * 2 + 1];
            g_adst[gr] = ddp[tid * 2] + ddp[tid * 2 + 1];
        }
    }
}

// ---------------- histogram ----------------
__global__ void hist_kernel(const void* __restrict__ adj) {
    int i = blockIdx.x * blockDim.x + threadIdx.x;
    if (i >= TOT_E) return;
    int is64 = g_is64;
    int d = (i < N_EDGES) ? load_adj(adj, (long long)N_EDGES + i, is64) : (i - N_EDGES);
    atomicAdd(&g_deg[d], 1);
}

// ---------------- device-wide scan ----------------
__global__ void __launch_bounds__(1024) scan1_kernel() {
    __shared__ int ws[32];
    int tid = threadIdx.x, lane = tid & 31, wid = tid >> 5;
    int i = blockIdx.x * 1024 + tid;
    int v = (i < N_NODES) ? g_deg[i] : 0;
#pragma unroll
    for (int o = 16; o; o >>= 1) v += __shfl_down_sync(0xffffffffu, v, o);
    if (lane == 0) ws[wid] = v;
    __syncthreads();
    if (wid == 0) {
        int s = ws[lane];
#pragma unroll
        for (int o = 16; o; o >>= 1) s += __shfl_down_sync(0xffffffffu, s, o);
        if (lane == 0) g_part[blockIdx.x] = s;
    }
}
__global__ void scan2_kernel() {
    __shared__ int ws[4];
    int tid = threadIdx.x, lane = tid & 31, wid = tid >> 5;
    int v = (tid < NBLK_SCAN) ? g_part[tid] : 0;
    int incl = v;
#pragma unroll
    for (int o = 1; o < 32; o <<= 1) {
        int t = __shfl_up_sync(0xffffffffu, incl, o);
        if (lane >= o) incl += t;
    }
    if (lane == 31) ws[wid] = incl;
    __syncthreads();
    int base = 0;
    for (int w = 0; w < wid; w++) base += ws[w];
    if (tid < NBLK_SCAN) g_part[tid] = base + incl - v;
    if (tid == 127) g_off[N_NODES] = base + incl;
}
__global__ void __launch_bounds__(1024) scan3_kernel() {
    __shared__ int ws[32];
    int tid = threadIdx.x, lane = tid & 31, wid = tid >> 5;
    int i = blockIdx.x * 1024 + tid;
    int v = (i < N_NODES) ? g_deg[i] : 0;
    int incl = v;
#pragma unroll
    for (int o = 1; o < 32; o <<= 1) {
        int t = __shfl_up_sync(0xffffffffu, incl, o);
        if (lane >= o) incl += t;
    }
    if (lane == 31) ws[wid] = incl;
    __syncthreads();
    if (wid == 0) {
        int s = ws[lane];
        int sc = s;
#pragma unroll
        for (int o = 1; o < 32; o <<= 1) {
            int t = __shfl_up_sync(0xffffffffu, sc, o);
            if (lane >= o) sc += t;
        }
        ws[lane] = sc - s;
    }
    __syncthreads();
    int excl = g_part[blockIdx.x] + ws[wid] + incl - v;
    if (i < N_NODES) { g_off[i] = excl; g_cur[i] = excl; }
}

// ---------------- scatter ----------------
__global__ void scatter_kernel(const void* __restrict__ adj) {
    int i = blockIdx.x * blockDim.x + threadIdx.x;
    if (i >= TOT_E) return;
    int is64 = g_is64;
    int s, d;
    if (i < N_EDGES) {
        s = load_adj(adj, i, is64);
        d = load_adj(adj, (long long)N_EDGES + i, is64);
    } else {
        s = i - N_EDGES;
        d = s;
    }
    float e = g_asrc[s] + g_adst[d];
    e = (e > 0.f) ? e : 0.2f * e;
    float ex = __expf(e);
    int pos = atomicAdd(&g_cur[d], 1);
    g_ssrc[pos] = s;
    g_sexp[pos] = ex;
}

// ---------------- aggregation (fp16 gather) ----------------
__global__ void agg_kernel(const float* __restrict__ bias, float* __restrict__ out) {
    int w = (blockIdx.x * blockDim.x + threadIdx.x) >> 5;
    int lane = threadIdx.x & 31;
    if (w >= N_NODES) return;
    int st = g_off[w], en = g_off[w + 1];
    float4 acc = make_float4(0.f, 0.f, 0.f, 0.f);
    float ssum = 0.f;
    for (int j = st; j < en; j++) {
        int s = g_ssrc[j];
        float ex = g_sexp[j];
        uint2 raw = *(const uint2*)&g_xh[(size_t)s * HID + lane * 4];
        __half2 p0 = *reinterpret_cast<__half2*>(&raw.x);
        __half2 p1 = *reinterpret_cast<__half2*>(&raw.y);
        float2 f0 = __half22float2(p0);
        float2 f1 = __half22float2(p1);
        ssum += ex;
        acc.x += ex * f0.x;
        acc.y += ex * f0.y;
        acc.z += ex * f1.x;
        acc.w += ex * f1.y;
    }
    float inv = 1.f / (ssum + 1e-16f);
    float4 b = *(const float4*)&bias[lane * 4];
    float4 o;
    o.x = acc.x * inv + b.x;
    o.y = acc.y * inv + b.y;
    o.z = acc.z * inv + b.z;
    o.w = acc.w * inv + b.w;
    o.x = (o.x > 0.f) ? o.x : 0.25f * o.x;
    o.y = (o.y > 0.f) ? o.y : 0.25f * o.y;
    o.z = (o.z > 0.f) ? o.z : 0.25f * o.z;
    o.w = (o.w > 0.f) ? o.w : 0.25f * o.w;
    *(float4*)&out[(size_t)w * HID + lane * 4] = o;
}

// ---------------- launcher ----------------
extern "C" void kernel_launch(void* const* d_in, const int* in_sizes, int n_in,
                              void* d_out, int out_size) {
    const float* data   = (const float*)d_in[0];
    const void*  adj    = (const void*)d_in[1];
    const float* W      = (const float*)d_in[2];
    const float* attsrc = (const float*)d_in[3];
    const float* attdst = (const float*)d_in[4];
    const float* bias   = (const float*)d_in[5];
    float* out = (float*)d_out;

    cudaFuncSetAttribute(gemm_kernel, cudaFuncAttributeMaxDynamicSharedMemorySize, S_BYTES);

    detect_kernel<<<1, 1>>>(adj);
    zero_kernel<<<(N_NODES + 255) / 256, 256>>>();
    wprep_kernel<<<(IN_F * HID + 255) / 256, 256>>>(W);
    gemm_kernel<<<(N_NODES + TILE_M - 1) / TILE_M, 256, S_BYTES>>>(data, attsrc, attdst);
    hist_kernel<<<(TOT_E + 255) / 256, 256>>>(adj);
    scan1_kernel<<<NBLK_SCAN, 1024>>>();
    scan2_kernel<<<1, 128>>>();
    scan3_kernel<<<NBLK_SCAN, 1024>>>();
    scatter_kernel<<<(TOT_E + 255) / 256, 256>>>(adj);
    agg_kernel<<<(N_NODES * 32 + 255) / 256, 256>>>(bias, out);
}

// round 7
// speedup vs baseline: 1.0303x; 1.0303x over previous
#include <cuda_runtime.h>
#include <cuda_bf16.h>
#include <cuda_fp16.h>
#include <cstdint>

#define N_NODES 100000
#define N_EDGES 3200000
#define TOT_E   (N_EDGES + N_NODES)
#define IN_F    512
#define HID     128
#define TILE_M  128
#define KC      32
#define NCHUNK  (IN_F / KC)     // 16
#define NBLK_SCAN 98

#define A_LD 40                       // elems (32 + 8 pad)
#define W_LD 136                      // elems (128 + 8 pad)
#define ABUF (TILE_M * A_LD)          // 5120 elems
#define WBUF (KC * W_LD)              // 4352 elems
#define BUFE (2 * ABUF + 2 * WBUF)    // 18944 elems per buffer
#define S_BYTES (2 * BUFE * 2)        // 75776 bytes

// ---------------- scratch ----------------
__device__ __align__(16) __half g_xh[(size_t)N_NODES * HID];   // fp16 feature cache
__device__ float g_asrc[N_NODES];
__device__ float g_adst[N_NODES];
__device__ int   g_deg[N_NODES];
__device__ int   g_off[N_NODES + 1];
__device__ int   g_cur[N_NODES];
__device__ int   g_ssrc[TOT_E];
__device__ float g_sexp[TOT_E];
__device__ int   g_is64;
__device__ __align__(16) __nv_bfloat16 g_wbh[IN_F * HID];  // W hi [k][n]
__device__ __align__(16) __nv_bfloat16 g_wbl[IN_F * HID];  // W lo [k][n]
__device__ int   g_part[128];

// ---------------- helpers ----------------
__device__ __forceinline__ uint32_t smem_u32(const void* p) {
    uint32_t a;
    asm("{ .reg .u64 t; cvta.to.shared.u64 t, %1; cvt.u32.u64 %0, t; }" : "=r"(a) : "l"(p));
    return a;
}
__device__ __forceinline__ void ldsm4(uint32_t* r, uint32_t addr) {
    asm volatile("ldmatrix.sync.aligned.m8n8.x4.shared.b16 {%0,%1,%2,%3}, [%4];"
                 : "=r"(r[0]), "=r"(r[1]), "=r"(r[2]), "=r"(r[3]) : "r"(addr));
}
__device__ __forceinline__ void ldsm4t(uint32_t* r, uint32_t addr) {
    asm volatile("ldmatrix.sync.aligned.m8n8.x4.trans.shared.b16 {%0,%1,%2,%3}, [%4];"
                 : "=r"(r[0]), "=r"(r[1]), "=r"(r[2]), "=r"(r[3]) : "r"(addr));
}
__device__ __forceinline__ void mma16816(float* c, const uint32_t* a, const uint32_t* b) {
    asm volatile("mma.sync.aligned.m16n8k16.row.col.f32.bf16.bf16.f32 "
                 "{%0,%1,%2,%3}, {%4,%5,%6,%7}, {%8,%9}, {%0,%1,%2,%3};"
                 : "+f"(c[0]), "+f"(c[1]), "+f"(c[2]), "+f"(c[3])
                 : "r"(a[0]), "r"(a[1]), "r"(a[2]), "r"(a[3]), "r"(b[0]), "r"(b[1]));
}
__device__ __forceinline__ void cp16(uint32_t dst, const void* src) {
    asm volatile("cp.async.ca.shared.global [%0], [%1], 16;" :: "r"(dst), "l"(src));
}
__device__ __forceinline__ void cp_commit() {
    asm volatile("cp.async.commit_group;" ::: "memory");
}
__device__ __forceinline__ void cp_wait_all() {
    asm volatile("cp.async.wait_group 0;" ::: "memory");
}

// ---------------- adj helpers ----------------
__device__ __forceinline__ int load_adj(const void* adj, long long i, int is64) {
    if (is64) return (int)((const long long*)adj)[i];
    return ((const int*)adj)[i];
}
__global__ void detect_kernel(const void* adj) {
    const int* p = (const int*)adj;
    int acc = 0;
#pragma unroll
    for (int k = 0; k < 64; k++) acc |= p[2 * k + 1];
    for (int k = 0; k < 64; k++) acc |= p[2 * (k * 9973 + 1000) + 1];
    g_is64 = (acc == 0) ? 1 : 0;
}
__global__ void zero_kernel() {
    int i = blockIdx.x * blockDim.x + threadIdx.x;
    if (i < N_NODES) g_deg[i] = 0;
}

// ---------------- W split prep ----------------
__global__ void wprep_kernel(const float* __restrict__ W) {
    int i = blockIdx.x * blockDim.x + threadIdx.x;
    if (i >= IN_F * HID) return;
    float v = W[i];
    __nv_bfloat16 h = __float2bfloat16(v);
    float r = v - __bfloat162float(h);
    g_wbh[i] = h;
    g_wbl[i] = __float2bfloat16(r);
}

// ---------------- pipelined HMMA GEMM, 2 CTAs/SM ----------------
__global__ void __launch_bounds__(256, 2) gemm_kernel(const float* __restrict__ A,
                                                      const float* __restrict__ attsrc,
                                                      const float* __restrict__ attdst) {
    extern __shared__ __nv_bfloat16 sm[];
    const int tid = threadIdx.x, lane = tid & 31, wid = tid >> 5;
    const int row0 = blockIdx.x * TILE_M;
    const int warp_m = wid & 3, warp_n = wid >> 2;

    float acc[16][4];
#pragma unroll
    for (int t = 0; t < 16; t++)
#pragma unroll
        for (int j = 0; j < 4; j++) acc[t][j] = 0.f;

    // A staging coords: thread -> (row, k-half of 16)
    const int ar = tid >> 1, ah_ = tid & 1;
    const int agr = row0 + ar;
    // W cp.async coords: 512 16B-chunks per matrix per chunk; 2 per thread
    const int wrow0 = tid >> 4, wc16 = tid & 15;          // chunk ci = tid
    const int wrow1 = (tid + 256) >> 4;                   // chunk ci = tid+256

    uint32_t h[8], l[8];

    // ---- load A chunk c (f32) and convert to packed hi/lo bf16 in regs ----
#define LOAD_A(c) do {                                                          \
        const int k0 = (c) * KC;                                                \
        if (agr < N_NODES) {                                                    \
            const float4* src = (const float4*)&A[(size_t)agr * IN_F + k0 + ah_ * 16]; \
            _Pragma("unroll")                                                   \
            for (int q = 0; q < 4; q++) {                                       \
                float4 v = src[q];                                              \
                __nv_bfloat162 hp0 = __floats2bfloat162_rn(v.x, v.y);           \
                __nv_bfloat162 lp0 = __floats2bfloat162_rn(v.x - __low2float(hp0), \
                                                           v.y - __high2float(hp0)); \
                __nv_bfloat162 hp1 = __floats2bfloat162_rn(v.z, v.w);           \
                __nv_bfloat162 lp1 = __floats2bfloat162_rn(v.z - __low2float(hp1), \
                                                           v.w - __high2float(hp1)); \
                h[2*q]   = *reinterpret_cast<uint32_t*>(&hp0);                  \
                l[2*q]   = *reinterpret_cast<uint32_t*>(&lp0);                  \
                h[2*q+1] = *reinterpret_cast<uint32_t*>(&hp1);                  \
                l[2*q+1] = *reinterpret_cast<uint32_t*>(&lp1);                  \
            }                                                                   \
        } else {                                                                \
            _Pragma("unroll")                                                   \
            for (int q = 0; q < 8; q++) { h[q] = 0u; l[q] = 0u; }               \
        }                                                                       \
    } while (0)

#define STORE_A(b) do {                                                         \
        __nv_bfloat16* dAh = sm + (b) * BUFE;                                   \
        __nv_bfloat16* dAl = dAh + ABUF;                                        \
        __nv_bfloat16* ph = &dAh[ar * A_LD + ah_ * 16];                         \
        __nv_bfloat16* pl = &dAl[ar * A_LD + ah_ * 16];                         \
        *(uint4*)(ph)     = make_uint4(h[0], h[1], h[2], h[3]);                 \
        *(uint4*)(ph + 8) = make_uint4(h[4], h[5], h[6], h[7]);                 \
        *(uint4*)(pl)     = make_uint4(l[0], l[1], l[2], l[3]);                 \
        *(uint4*)(pl + 8) = make_uint4(l[4], l[5], l[6], l[7]);                 \
    } while (0)

    // ---- issue cp.async for W chunk c into buffer b ----
#define ISSUE_W(c, b) do {                                                      \
        const int k0 = (c) * KC;                                                \
        uint32_t wh = smem_u32(sm + (b) * BUFE + 2 * ABUF);                     \
        uint32_t wl = wh + WBUF * 2;                                            \
        cp16(wh + (wrow0 * W_LD + wc16 * 8) * 2,                                \
             &g_wbh[(size_t)(k0 + wrow0) * HID + wc16 * 8]);                    \
        cp16(wh + (wrow1 * W_LD + wc16 * 8) * 2,                                \
             &g_wbh[(size_t)(k0 + wrow1) * HID + wc16 * 8]);                    \
        cp16(wl + (wrow0 * W_LD + wc16 * 8) * 2,                                \
             &g_wbl[(size_t)(k0 + wrow0) * HID + wc16 * 8]);                    \
        cp16(wl + (wrow1 * W_LD + wc16 * 8) * 2,                                \
             &g_wbl[(size_t)(k0 + wrow1) * HID + wc16 * 8]);                    \
        cp_commit();                                                            \
    } while (0)

    // prologue: chunk 0
    ISSUE_W(0, 0);
    LOAD_A(0);
    STORE_A(0);
    cp_wait_all();
    __syncthreads();

    for (int c = 0; c < NCHUNK; c++) {
        const int buf = c & 1;
        if (c < NCHUNK - 1) {
            ISSUE_W(c + 1, buf ^ 1);    // async into alt buffer
            LOAD_A(c + 1);              // LDGs in flight during MMAs
        }

        const __nv_bfloat16* Ah = sm + buf * BUFE;
        const __nv_bfloat16* Al = Ah + ABUF;
        const __nv_bfloat16* Wh = Al + ABUF;
        const __nv_bfloat16* Wl = Wh + WBUF;

#pragma unroll
        for (int ks = 0; ks < 2; ks++) {
            uint32_t a_h[2][4], a_l[2][4];
#pragma unroll
            for (int mi = 0; mi < 2; mi++) {
                uint32_t aoff = (warp_m * 32 + mi * 16 + (lane & 15)) * A_LD
                              + ks * 16 + (lane >> 4) * 8;
                ldsm4(a_h[mi], smem_u32(&Ah[aoff]));
                ldsm4(a_l[mi], smem_u32(&Al[aoff]));
            }
#pragma unroll
            for (int nt = 0; nt < 4; nt++) {
                uint32_t b_h[4], b_l[4];
                uint32_t woff = (ks * 16 + (lane & 15)) * W_LD
                              + warp_n * 64 + nt * 16 + (lane >> 4) * 8;
                ldsm4t(b_h, smem_u32(&Wh[woff]));
                ldsm4t(b_l, smem_u32(&Wl[woff]));
#pragma unroll
                for (int mi = 0; mi < 2; mi++) {
                    int t = mi * 8 + nt * 2;
                    mma16816(acc[t],     a_h[mi], b_h);
                    mma16816(acc[t + 1], a_h[mi], b_h + 2);
                    mma16816(acc[t],     a_l[mi], b_h);
                    mma16816(acc[t + 1], a_l[mi], b_h + 2);
                    mma16816(acc[t],     a_h[mi], b_l);
                    mma16816(acc[t + 1], a_h[mi], b_l + 2);
                }
            }
        }
        if (c < NCHUNK - 1) {
            STORE_A(buf ^ 1);
            cp_wait_all();              // W(c+1) landed; overlapped with MMAs above
        }
        __syncthreads();
    }

    // ---- epilogue: fp16 g_xh + fused attention dots ----
    float sd[2][2] = {{0.f, 0.f}, {0.f, 0.f}};
    float dd[2][2] = {{0.f, 0.f}, {0.f, 0.f}};
#pragma unroll
    for (int mi = 0; mi < 2; mi++) {
        const int rlo = row0 + warp_m * 32 + mi * 16 + (lane >> 2);
        const int rhi = rlo + 8;
#pragma unroll
        for (int nt = 0; nt < 4; nt++) {
#pragma unroll
            for (int hh = 0; hh < 2; hh++) {
                int t = mi * 8 + nt * 2 + hh;
                int col = warp_n * 64 + nt * 16 + hh * 8 + (lane & 3) * 2;
                float as0 = __ldg(&attsrc[col]), as1 = __ldg(&attsrc[col + 1]);
                float ad0 = __ldg(&attdst[col]), ad1 = __ldg(&attdst[col + 1]);
                float2 v0 = make_float2(acc[t][0], acc[t][1]);
                float2 v1 = make_float2(acc[t][2], acc[t][3]);
                sd[mi][0] += v0.x * as0 + v0.y * as1;
                dd[mi][0] += v0.x * ad0 + v0.y * ad1;
                sd[mi][1] += v1.x * as0 + v1.y * as1;
                dd[mi][1] += v1.x * ad0 + v1.y * ad1;
                if (rlo < N_NODES) {
                    __half2 p = __float22half2_rn(v0);
                    *(uint32_t*)&g_xh[(size_t)rlo * HID + col] = *(uint32_t*)&p;
                }
                if (rhi < N_NODES) {
                    __half2 p = __float22half2_rn(v1);
                    *(uint32_t*)&g_xh[(size_t)rhi * HID + col] = *(uint32_t*)&p;
                }
            }
        }
    }
#pragma unroll
    for (int o = 1; o <= 2; o <<= 1) {
#pragma unroll
        for (int mi = 0; mi < 2; mi++)
#pragma unroll
            for (int hh = 0; hh < 2; hh++) {
                sd[mi][hh] += __shfl_xor_sync(0xffffffffu, sd[mi][hh], o);
                dd[mi][hh] += __shfl_xor_sync(0xffffffffu, dd[mi][hh], o);
            }
    }
    float* sdp = (float*)sm;
    float* ddp = sdp + 256;
    if ((lane & 3) == 0) {
#pragma unroll
        for (int mi = 0; mi < 2; mi++)
#pragma unroll
            for (int hh = 0; hh < 2; hh++) {
                int rt = warp_m * 32 + mi * 16 + (lane >> 2) + hh * 8;
                sdp[rt * 2 + warp_n] = sd[mi][hh];
                ddp[rt * 2 + warp_n] = dd[mi][hh];
            }
    }
    __syncthreads();
    if (tid < 128) {
        int gr = row0 + tid;
        if (gr < N_NODES) {
            g_asrc[gr] = sdp[tid * 2] + sdp[tid * 2 + 1];
            g_adst[gr] = ddp[tid * 2] + ddp[tid * 2 + 1];
        }
    }
}

// ---------------- histogram ----------------
__global__ void hist_kernel(const void* __restrict__ adj) {
    int i = blockIdx.x * blockDim.x + threadIdx.x;
    if (i >= TOT_E) return;
    int is64 = g_is64;
    int d = (i < N_EDGES) ? load_adj(adj, (long long)N_EDGES + i, is64) : (i - N_EDGES);
    atomicAdd(&g_deg[d], 1);
}

// ---------------- device-wide scan ----------------
__global__ void __launch_bounds__(1024) scan1_kernel() {
    __shared__ int ws[32];
    int tid = threadIdx.x, lane = tid & 31, wid = tid >> 5;
    int i = blockIdx.x * 1024 + tid;
    int v = (i < N_NODES) ? g_deg[i] : 0;
#pragma unroll
    for (int o = 16; o; o >>= 1) v += __shfl_down_sync(0xffffffffu, v, o);
    if (lane == 0) ws[wid] = v;
    __syncthreads();
    if (wid == 0) {
        int s = ws[lane];
#pragma unroll
        for (int o = 16; o; o >>= 1) s += __shfl_down_sync(0xffffffffu, s, o);
        if (lane == 0) g_part[blockIdx.x] = s;
    }
}
__global__ void scan2_kernel() {
    __shared__ int ws[4];
    int tid = threadIdx.x, lane = tid & 31, wid = tid >> 5;
    int v = (tid < NBLK_SCAN) ? g_part[tid] : 0;
    int incl = v;
#pragma unroll
    for (int o = 1; o < 32; o <<= 1) {
        int t = __shfl_up_sync(0xffffffffu, incl, o);
        if (lane >= o) incl += t;
    }
    if (lane == 31) ws[wid] = incl;
    __syncthreads();
    int base = 0;
    for (int w = 0; w < wid; w++) base += ws[w];
    if (tid < NBLK_SCAN) g_part[tid] = base + incl - v;
    if (tid == 127) g_off[N_NODES] = base + incl;
}
__global__ void __launch_bounds__(1024) scan3_kernel() {
    __shared__ int ws[32];
    int tid = threadIdx.x, lane = tid & 31, wid = tid >> 5;
    int i = blockIdx.x * 1024 + tid;
    int v = (i < N_NODES) ? g_deg[i] : 0;
    int incl = v;
#pragma unroll
    for (int o = 1; o < 32; o <<= 1) {
        int t = __shfl_up_sync(0xffffffffu, incl, o);
        if (lane >= o) incl += t;
    }
    if (lane == 31) ws[wid] = incl;
    __syncthreads();
    if (wid == 0) {
        int s = ws[lane];
        int sc = s;
#pragma unroll
        for (int o = 1; o < 32; o <<= 1) {
            int t = __shfl_up_sync(0xffffffffu, sc, o);
            if (lane >= o) sc += t;
        }
        ws[lane] = sc - s;
    }
    __syncthreads();
    int excl = g_part[blockIdx.x] + ws[wid] + incl - v;
    if (i < N_NODES) { g_off[i] = excl; g_cur[i] = excl; }
}

// ---------------- scatter ----------------
__global__ void scatter_kernel(const void* __restrict__ adj) {
    int i = blockIdx.x * blockDim.x + threadIdx.x;
    if (i >= TOT_E) return;
    int is64 = g_is64;
    int s, d;
    if (i < N_EDGES) {
        s = load_adj(adj, i, is64);
        d = load_adj(adj, (long long)N_EDGES + i, is64);
    } else {
        s = i - N_EDGES;
        d = s;
    }
    float e = g_asrc[s] + g_adst[d];
    e = (e > 0.f) ? e : 0.2f * e;
    float ex = __expf(e);
    int pos = atomicAdd(&g_cur[d], 1);
    g_ssrc[pos] = s;
    g_sexp[pos] = ex;
}

// ---------------- aggregation (fp16 gather) ----------------
__global__ void agg_kernel(const float* __restrict__ bias, float* __restrict__ out) {
    int w = (blockIdx.x * blockDim.x + threadIdx.x) >> 5;
    int lane = threadIdx.x & 31;
    if (w >= N_NODES) return;
    int st = g_off[w], en = g_off[w + 1];
    float4 acc = make_float4(0.f, 0.f, 0.f, 0.f);
    float ssum = 0.f;
    for (int j = st; j < en; j++) {
        int s = g_ssrc[j];
        float ex = g_sexp[j];
        uint2 raw = *(const uint2*)&g_xh[(size_t)s * HID + lane * 4];
        __half2 p0 = *reinterpret_cast<__half2*>(&raw.x);
        __half2 p1 = *reinterpret_cast<__half2*>(&raw.y);
        float2 f0 = __half22float2(p0);
        float2 f1 = __half22float2(p1);
        ssum += ex;
        acc.x += ex * f0.x;
        acc.y += ex * f0.y;
        acc.z += ex * f1.x;
        acc.w += ex * f1.y;
    }
    float inv = 1.f / (ssum + 1e-16f);
    float4 b = *(const float4*)&bias[lane * 4];
    float4 o;
    o.x = acc.x * inv + b.x;
    o.y = acc.y * inv + b.y;
    o.z = acc.z * inv + b.z;
    o.w = acc.w * inv + b.w;
    o.x = (o.x > 0.f) ? o.x : 0.25f * o.x;
    o.y = (o.y > 0.f) ? o.y : 0.25f * o.y;
    o.z = (o.z > 0.f) ? o.z : 0.25f * o.z;
    o.w = (o.w > 0.f) ? o.w : 0.25f * o.w;
    *(float4*)&out[(size_t)w * HID + lane * 4] = o;
}

// ---------------- launcher ----------------
extern "C" void kernel_launch(void* const* d_in, const int* in_sizes, int n_in,
                              void* d_out, int out_size) {
    const float* data   = (const float*)d_in[0];
    const void*  adj    = (const void*)d_in[1];
    const float* W      = (const float*)d_in[2];
    const float* attsrc = (const float*)d_in[3];
    const float* attdst = (const float*)d_in[4];
    const float* bias   = (const float*)d_in[5];
    float* out = (float*)d_out;

    cudaFuncSetAttribute(gemm_kernel, cudaFuncAttributeMaxDynamicSharedMemorySize, S_BYTES);

    detect_kernel<<<1, 1>>>(adj);
    zero_kernel<<<(N_NODES + 255) / 256, 256>>>();
    wprep_kernel<<<(IN_F * HID + 255) / 256, 256>>>(W);
    gemm_kernel<<<(N_NODES + TILE_M - 1) / TILE_M, 256, S_BYTES>>>(data, attsrc, attdst);
    hist_kernel<<<(TOT_E + 255) / 256, 256>>>(adj);
    scan1_kernel<<<NBLK_SCAN, 1024>>>();
    scan2_kernel<<<1, 128>>>();
    scan3_kernel<<<NBLK_SCAN, 1024>>>();
    scatter_kernel<<<(TOT_E + 255) / 256, 256>>>(adj);
    agg_kernel<<<(N_NODES * 32 + 255) / 256, 256>>>(bias, out);
}

// round 8
// speedup vs baseline: 1.1001x; 1.0677x over previous
#include <cuda_runtime.h>
#include <cuda_bf16.h>
#include <cuda_fp16.h>
#include <cstdint>

#define N_NODES 100000
#define N_EDGES 3200000
#define TOT_E   (N_EDGES + N_NODES)
#define IN_F    512
#define HID     128
#define TILE_M  128
#define KC      32
#define NCHUNK  (IN_F / KC)     // 16
#define NBLK_SCAN 98

#define A_LD 40                       // elems (32 + 8 pad)
#define W_LD 136                      // elems (128 + 8 pad)
#define ABUF (TILE_M * A_LD)          // 5120 elems
#define WBUF (KC * W_LD)              // 4352 elems
#define BUFE (2 * ABUF + WBUF)        // 14592 elems per buffer (Ah, Al, Wh)
#define S_BYTES (2 * BUFE * 2)        // 58368 bytes

// ---------------- scratch ----------------
__device__ __align__(16) __half g_xh[(size_t)N_NODES * HID];   // fp16 feature cache
__device__ float g_asrc[N_NODES];
__device__ float g_adst[N_NODES];
__device__ int   g_deg[N_NODES];
__device__ int   g_off[N_NODES + 1];
__device__ int   g_cur[N_NODES];
__device__ int   g_ssrc[TOT_E];
__device__ float g_sexp[TOT_E];
__device__ int   g_is64;
__device__ __align__(16) __half g_wfh[IN_F * HID];   // W fp16 [k][n]
__device__ int   g_part[128];

// ---------------- helpers ----------------
__device__ __forceinline__ uint32_t smem_u32(const void* p) {
    uint32_t a;
    asm("{ .reg .u64 t; cvta.to.shared.u64 t, %1; cvt.u32.u64 %0, t; }" : "=r"(a) : "l"(p));
    return a;
}
__device__ __forceinline__ void ldsm4(uint32_t* r, uint32_t addr) {
    asm volatile("ldmatrix.sync.aligned.m8n8.x4.shared.b16 {%0,%1,%2,%3}, [%4];"
                 : "=r"(r[0]), "=r"(r[1]), "=r"(r[2]), "=r"(r[3]) : "r"(addr));
}
__device__ __forceinline__ void ldsm4t(uint32_t* r, uint32_t addr) {
    asm volatile("ldmatrix.sync.aligned.m8n8.x4.trans.shared.b16 {%0,%1,%2,%3}, [%4];"
                 : "=r"(r[0]), "=r"(r[1]), "=r"(r[2]), "=r"(r[3]) : "r"(addr));
}
__device__ __forceinline__ void mma16816(float* c, const uint32_t* a, const uint32_t* b) {
    asm volatile("mma.sync.aligned.m16n8k16.row.col.f32.f16.f16.f32 "
                 "{%0,%1,%2,%3}, {%4,%5,%6,%7}, {%8,%9}, {%0,%1,%2,%3};"
                 : "+f"(c[0]), "+f"(c[1]), "+f"(c[2]), "+f"(c[3])
                 : "r"(a[0]), "r"(a[1]), "r"(a[2]), "r"(a[3]), "r"(b[0]), "r"(b[1]));
}
__device__ __forceinline__ void cp16(uint32_t dst, const void* src) {
    asm volatile("cp.async.ca.shared.global [%0], [%1], 16;" :: "r"(dst), "l"(src));
}
__device__ __forceinline__ void cp_commit() {
    asm volatile("cp.async.commit_group;" ::: "memory");
}
__device__ __forceinline__ void cp_wait_all() {
    asm volatile("cp.async.wait_group 0;" ::: "memory");
}

// ---------------- adj helpers ----------------
__device__ __forceinline__ int load_adj(const void* adj, long long i, int is64) {
    if (is64) return (int)((const long long*)adj)[i];
    return ((const int*)adj)[i];
}
__global__ void detect_kernel(const void* adj) {
    const int* p = (const int*)adj;
    int acc = 0;
#pragma unroll
    for (int k = 0; k < 64; k++) acc |= p[2 * k + 1];
    for (int k = 0; k < 64; k++) acc |= p[2 * (k * 9973 + 1000) + 1];
    g_is64 = (acc == 0) ? 1 : 0;
}
__global__ void zero_kernel() {
    int i = blockIdx.x * blockDim.x + threadIdx.x;
    if (i < N_NODES) g_deg[i] = 0;
}

// ---------------- W fp16 prep ----------------
__global__ void wprep_kernel(const float* __restrict__ W) {
    int i = blockIdx.x * blockDim.x + threadIdx.x;
    if (i >= IN_F * HID) return;
    g_wfh[i] = __float2half_rn(W[i]);
}

// ---------------- pipelined HMMA GEMM (2-term fp16 split), 2 CTAs/SM ----------------
__global__ void __launch_bounds__(256, 2) gemm_kernel(const float* __restrict__ A,
                                                      const float* __restrict__ attsrc,
                                                      const float* __restrict__ attdst) {
    extern __shared__ __half sm[];
    const int tid = threadIdx.x, lane = tid & 31, wid = tid >> 5;
    const int row0 = blockIdx.x * TILE_M;
    const int warp_m = wid & 3, warp_n = wid >> 2;

    float acc[16][4];
#pragma unroll
    for (int t = 0; t < 16; t++)
#pragma unroll
        for (int j = 0; j < 4; j++) acc[t][j] = 0.f;

    // A staging coords: thread -> (row, k-half of 16)
    const int ar = tid >> 1, ah_ = tid & 1;
    const int agr = row0 + ar;
    // W cp.async coords: 512 16B-chunks per K-chunk; 2 per thread
    const int wrow0 = tid >> 4, wc0 = (tid & 15) * 8;
    const int wrow1 = (tid + 256) >> 4;

    uint32_t h[8], l[8];

    // ---- load A chunk c (f32) and convert to packed hi/lo fp16 in regs ----
#define LOAD_A(c) do {                                                          \
        const int k0 = (c) * KC;                                                \
        if (agr < N_NODES) {                                                    \
            const float4* src = (const float4*)&A[(size_t)agr * IN_F + k0 + ah_ * 16]; \
            _Pragma("unroll")                                                   \
            for (int q = 0; q < 4; q++) {                                       \
                float4 v = src[q];                                              \
                __half2 hp0 = __floats2half2_rn(v.x, v.y);                      \
                __half2 lp0 = __floats2half2_rn(v.x - __low2float(hp0),         \
                                                v.y - __high2float(hp0));       \
                __half2 hp1 = __floats2half2_rn(v.z, v.w);                      \
                __half2 lp1 = __floats2half2_rn(v.z - __low2float(hp1),         \
                                                v.w - __high2float(hp1));       \
                h[2*q]   = *reinterpret_cast<uint32_t*>(&hp0);                  \
                l[2*q]   = *reinterpret_cast<uint32_t*>(&lp0);                  \
                h[2*q+1] = *reinterpret_cast<uint32_t*>(&hp1);                  \
                l[2*q+1] = *reinterpret_cast<uint32_t*>(&lp1);                  \
            }                                                                   \
        } else {                                                                \
            _Pragma("unroll")                                                   \
            for (int q = 0; q < 8; q++) { h[q] = 0u; l[q] = 0u; }               \
        }                                                                       \
    } while (0)

#define STORE_A(b) do {                                                         \
        __half* dAh = sm + (b) * BUFE;                                          \
        __half* dAl = dAh + ABUF;                                               \
        __half* ph = &dAh[ar * A_LD + ah_ * 16];                                \
        __half* pl = &dAl[ar * A_LD + ah_ * 16];                                \
        *(uint4*)(ph)     = make_uint4(h[0], h[1], h[2], h[3]);                 \
        *(uint4*)(ph + 8) = make_uint4(h[4], h[5], h[6], h[7]);                 \
        *(uint4*)(pl)     = make_uint4(l[0], l[1], l[2], l[3]);                 \
        *(uint4*)(pl + 8) = make_uint4(l[4], l[5], l[6], l[7]);                 \
    } while (0)

    // ---- issue cp.async for W chunk c into buffer b (512 x 16B, 2/thread) ----
#define ISSUE_W(c, b) do {                                                      \
        const int k0 = (c) * KC;                                                \
        uint32_t wh = smem_u32(sm + (b) * BUFE + 2 * ABUF);                     \
        cp16(wh + (wrow0 * W_LD + wc0) * 2,                                     \
             &g_wfh[(size_t)(k0 + wrow0) * HID + wc0]);                         \
        cp16(wh + (wrow1 * W_LD + wc0) * 2,                                     \
             &g_wfh[(size_t)(k0 + wrow1) * HID + wc0]);                         \
        cp_commit();                                                            \
    } while (0)

    ISSUE_W(0, 0);
    LOAD_A(0);
    STORE_A(0);
    cp_wait_all();
    __syncthreads();

    for (int c = 0; c < NCHUNK; c++) {
        const int buf = c & 1;
        if (c < NCHUNK - 1) {
            ISSUE_W(c + 1, buf ^ 1);
            LOAD_A(c + 1);
        }

        const __half* Ah = sm + buf * BUFE;
        const __half* Al = Ah + ABUF;
        const __half* Wh = Al + ABUF;

#pragma unroll
        for (int ks = 0; ks < 2; ks++) {
            uint32_t a_h[2][4], a_l[2][4];
#pragma unroll
            for (int mi = 0; mi < 2; mi++) {
                uint32_t aoff = (warp_m * 32 + mi * 16 + (lane & 15)) * A_LD
                              + ks * 16 + (lane >> 4) * 8;
                ldsm4(a_h[mi], smem_u32(&Ah[aoff]));
                ldsm4(a_l[mi], smem_u32(&Al[aoff]));
            }
#pragma unroll
            for (int nt = 0; nt < 4; nt++) {
                uint32_t b_h[4];
                uint32_t woff = (ks * 16 + (lane & 15)) * W_LD
                              + warp_n * 64 + nt * 16 + (lane >> 4) * 8;
                ldsm4t(b_h, smem_u32(&Wh[woff]));
#pragma unroll
                for (int mi = 0; mi < 2; mi++) {
                    int t = mi * 8 + nt * 2;
                    mma16816(acc[t],     a_h[mi], b_h);
                    mma16816(acc[t + 1], a_h[mi], b_h + 2);
                    mma16816(acc[t],     a_l[mi], b_h);
                    mma16816(acc[t + 1], a_l[mi], b_h + 2);
                }
            }
        }
        if (c < NCHUNK - 1) {
            STORE_A(buf ^ 1);
            cp_wait_all();
        }
        __syncthreads();
    }

    // ---- epilogue: fp16 g_xh + fused attention dots ----
    float sd[2][2] = {{0.f, 0.f}, {0.f, 0.f}};
    float dd[2][2] = {{0.f, 0.f}, {0.f, 0.f}};
#pragma unroll
    for (int mi = 0; mi < 2; mi++) {
        const int rlo = row0 + warp_m * 32 + mi * 16 + (lane >> 2);
        const int rhi = rlo + 8;
#pragma unroll
        for (int nt = 0; nt < 4; nt++) {
#pragma unroll
            for (int hh = 0; hh < 2; hh++) {
                int t = mi * 8 + nt * 2 + hh;
                int col = warp_n * 64 + nt * 16 + hh * 8 + (lane & 3) * 2;
                float as0 = __ldg(&attsrc[col]), as1 = __ldg(&attsrc[col + 1]);
                float ad0 = __ldg(&attdst[col]), ad1 = __ldg(&attdst[col + 1]);
                float2 v0 = make_float2(acc[t][0], acc[t][1]);
                float2 v1 = make_float2(acc[t][2], acc[t][3]);
                sd[mi][0] += v0.x * as0 + v0.y * as1;
                dd[mi][0] += v0.x * ad0 + v0.y * ad1;
                sd[mi][1] += v1.x * as0 + v1.y * as1;
                dd[mi][1] += v1.x * ad0 + v1.y * ad1;
                if (rlo < N_NODES) {
                    __half2 p = __float22half2_rn(v0);
                    *(uint32_t*)&g_xh[(size_t)rlo * HID + col] = *(uint32_t*)&p;
                }
                if (rhi < N_NODES) {
                    __half2 p = __float22half2_rn(v1);
                    *(uint32_t*)&g_xh[(size_t)rhi * HID + col] = *(uint32_t*)&p;
                }
            }
        }
    }
#pragma unroll
    for (int o = 1; o <= 2; o <<= 1) {
#pragma unroll
        for (int mi = 0; mi < 2; mi++)
#pragma unroll
            for (int hh = 0; hh < 2; hh++) {
                sd[mi][hh] += __shfl_xor_sync(0xffffffffu, sd[mi][hh], o);
                dd[mi][hh] += __shfl_xor_sync(0xffffffffu, dd[mi][hh], o);
            }
    }
    float* sdp = (float*)sm;
    float* ddp = sdp + 256;
    if ((lane & 3) == 0) {
#pragma unroll
        for (int mi = 0; mi < 2; mi++)
#pragma unroll
            for (int hh = 0; hh < 2; hh++) {
                int rt = warp_m * 32 + mi * 16 + (lane >> 2) + hh * 8;
                sdp[rt * 2 + warp_n] = sd[mi][hh];
                ddp[rt * 2 + warp_n] = dd[mi][hh];
            }
    }
    __syncthreads();
    if (tid < 128) {
        int gr = row0 + tid;
        if (gr < N_NODES) {
            g_asrc[gr] = sdp[tid * 2] + sdp[tid * 2 + 1];
            g_adst[gr] = ddp[tid * 2] + ddp[tid * 2 + 1];
        }
    }
}

// ---------------- histogram ----------------
__global__ void hist_kernel(const void* __restrict__ adj) {
    int i = blockIdx.x * blockDim.x + threadIdx.x;
    if (i >= TOT_E) return;
    int is64 = g_is64;
    int d = (i < N_EDGES) ? load_adj(adj, (long long)N_EDGES + i, is64) : (i - N_EDGES);
    atomicAdd(&g_deg[d], 1);
}

// ---------------- device-wide scan ----------------
__global__ void __launch_bounds__(1024) scan1_kernel() {
    __shared__ int ws[32];
    int tid = threadIdx.x, lane = tid & 31, wid = tid >> 5;
    int i = blockIdx.x * 1024 + tid;
    int v = (i < N_NODES) ? g_deg[i] : 0;
#pragma unroll
    for (int o = 16; o; o >>= 1) v += __shfl_down_sync(0xffffffffu, v, o);
    if (lane == 0) ws[wid] = v;
    __syncthreads();
    if (wid == 0) {
        int s = ws[lane];
#pragma unroll
        for (int o = 16; o; o >>= 1) s += __shfl_down_sync(0xffffffffu, s, o);
        if (lane == 0) g_part[blockIdx.x] = s;
    }
}
__global__ void scan2_kernel() {
    __shared__ int ws[4];
    int tid = threadIdx.x, lane = tid & 31, wid = tid >> 5;
    int v = (tid < NBLK_SCAN) ? g_part[tid] : 0;
    int incl = v;
#pragma unroll
    for (int o = 1; o < 32; o <<= 1) {
        int t = __shfl_up_sync(0xffffffffu, incl, o);
        if (lane >= o) incl += t;
    }
    if (lane == 31) ws[wid] = incl;
    __syncthreads();
    int base = 0;
    for (int w = 0; w < wid; w++) base += ws[w];
    if (tid < NBLK_SCAN) g_part[tid] = base + incl - v;
    if (tid == 127) g_off[N_NODES] = base + incl;
}
__global__ void __launch_bounds__(1024) scan3_kernel() {
    __shared__ int ws[32];
    int tid = threadIdx.x, lane = tid & 31, wid = tid >> 5;
    int i = blockIdx.x * 1024 + tid;
    int v = (i < N_NODES) ? g_deg[i] : 0;
    int incl = v;
#pragma unroll
    for (int o = 1; o < 32; o <<= 1) {
        int t = __shfl_up_sync(0xffffffffu, incl, o);
        if (lane >= o) incl += t;
    }
    if (lane == 31) ws[wid] = incl;
    __syncthreads();
    if (wid == 0) {
        int s = ws[lane];
        int sc = s;
#pragma unroll
        for (int o = 1; o < 32; o <<= 1) {
            int t = __shfl_up_sync(0xffffffffu, sc, o);
            if (lane >= o) sc += t;
        }
        ws[lane] = sc - s;
    }
    __syncthreads();
    int excl = g_part[blockIdx.x] + ws[wid] + incl - v;
    if (i < N_NODES) { g_off[i] = excl; g_cur[i] = excl; }
}

// ---------------- scatter ----------------
__global__ void scatter_kernel(const void* __restrict__ adj) {
    int i = blockIdx.x * blockDim.x + threadIdx.x;
    if (i >= TOT_E) return;
    int is64 = g_is64;
    int s, d;
    if (i < N_EDGES) {
        s = load_adj(adj, i, is64);
        d = load_adj(adj, (long long)N_EDGES + i, is64);
    } else {
        s = i - N_EDGES;
        d = s;
    }
    float e = g_asrc[s] + g_adst[d];
    e = (e > 0.f) ? e : 0.2f * e;
    float ex = __expf(e);
    int pos = atomicAdd(&g_cur[d], 1);
    g_ssrc[pos] = s;
    g_sexp[pos] = ex;
}

// ---------------- aggregation (fp16 gather) ----------------
__global__ void agg_kernel(const float* __restrict__ bias, float* __restrict__ out) {
    int w = (blockIdx.x * blockDim.x + threadIdx.x) >> 5;
    int lane = threadIdx.x & 31;
    if (w >= N_NODES) return;
    int st = g_off[w], en = g_off[w + 1];
    float4 acc = make_float4(0.f, 0.f, 0.f, 0.f);
    float ssum = 0.f;
    for (int j = st; j < en; j++) {
        int s = g_ssrc[j];
        float ex = g_sexp[j];
        uint2 raw = *(const uint2*)&g_xh[(size_t)s * HID + lane * 4];
        __half2 p0 = *reinterpret_cast<__half2*>(&raw.x);
        __half2 p1 = *reinterpret_cast<__half2*>(&raw.y);
        float2 f0 = __half22float2(p0);
        float2 f1 = __half22float2(p1);
        ssum += ex;
        acc.x += ex * f0.x;
        acc.y += ex * f0.y;
        acc.z += ex * f1.x;
        acc.w += ex * f1.y;
    }
    float inv = 1.f / (ssum + 1e-16f);
    float4 b = *(const float4*)&bias[lane * 4];
    float4 o;
    o.x = acc.x * inv + b.x;
    o.y = acc.y * inv + b.y;
    o.z = acc.z * inv + b.z;
    o.w = acc.w * inv + b.w;
    o.x = (o.x > 0.f) ? o.x : 0.25f * o.x;
    o.y = (o.y > 0.f) ? o.y : 0.25f * o.y;
    o.z = (o.z > 0.f) ? o.z : 0.25f * o.z;
    o.w = (o.w > 0.f) ? o.w : 0.25f * o.w;
    *(float4*)&out[(size_t)w * HID + lane * 4] = o;
}

// ---------------- launcher ----------------
extern "C" void kernel_launch(void* const* d_in, const int* in_sizes, int n_in,
                              void* d_out, int out_size) {
    const float* data   = (const float*)d_in[0];
    const void*  adj    = (const void*)d_in[1];
    const float* W      = (const float*)d_in[2];
    const float* attsrc = (const float*)d_in[3];
    const float* attdst = (const float*)d_in[4];
    const float* bias   = (const float*)d_in[5];
    float* out = (float*)d_out;

    cudaFuncSetAttribute(gemm_kernel, cudaFuncAttributeMaxDynamicSharedMemorySize, S_BYTES);

    detect_kernel<<<1, 1>>>(adj);
    zero_kernel<<<(N_NODES + 255) / 256, 256>>>();
    wprep_kernel<<<(IN_F * HID + 255) / 256, 256>>>(W);
    gemm_kernel<<<(N_NODES + TILE_M - 1) / TILE_M, 256, S_BYTES>>>(data, attsrc, attdst);
    hist_kernel<<<(TOT_E + 255) / 256, 256>>>(adj);
    scan1_kernel<<<NBLK_SCAN, 1024>>>();
    scan2_kernel<<<1, 128>>>();
    scan3_kernel<<<NBLK_SCAN, 1024>>>();
    scatter_kernel<<<(TOT_E + 255) / 256, 256>>>(adj);
    agg_kernel<<<(N_NODES * 32 + 255) / 256, 256>>>(bias, out);
}

// round 9
// speedup vs baseline: 1.2419x; 1.1289x over previous
#include <cuda_runtime.h>
#include <cuda_bf16.h>
#include <cuda_fp16.h>
#include <cstdint>

#define N_NODES 100000
#define N_EDGES 3200000
#define TOT_E   (N_EDGES + N_NODES)
#define IN_F    512
#define HID     128
#define TILE_M  128
#define KC      64
#define NCHUNK  (IN_F / KC)     // 8
#define NBLK_SCAN 98

#define A_LD 72                       // elems (64 + 8 pad)
#define W_LD 136                      // elems (128 + 8 pad)
#define ABUF (TILE_M * A_LD)          // 9216 elems
#define WBUF (KC * W_LD)              // 8704 elems
#define BUFE (ABUF + WBUF)            // 17920 elems per buffer
#define S_BYTES (2 * BUFE * 2)        // 71680 bytes

// ---------------- scratch ----------------
__device__ __align__(16) __half g_xh[(size_t)N_NODES * HID];   // fp16 feature cache
__device__ float g_asrc[N_NODES];
__device__ float g_adst[N_NODES];
__device__ int   g_deg[N_NODES];
__device__ int   g_off[N_NODES + 1];
__device__ int   g_cur[N_NODES];
__device__ __align__(16) int2 g_edge[TOT_E];   // (src, exp-bits) sorted by dst
__device__ int   g_is64;
__device__ __align__(16) __half g_wfh[IN_F * HID];   // W fp16 [k][n]
__device__ int   g_part[128];

// ---------------- helpers ----------------
__device__ __forceinline__ uint32_t smem_u32(const void* p) {
    uint32_t a;
    asm("{ .reg .u64 t; cvta.to.shared.u64 t, %1; cvt.u32.u64 %0, t; }" : "=r"(a) : "l"(p));
    return a;
}
__device__ __forceinline__ void ldsm4(uint32_t* r, uint32_t addr) {
    asm volatile("ldmatrix.sync.aligned.m8n8.x4.shared.b16 {%0,%1,%2,%3}, [%4];"
                 : "=r"(r[0]), "=r"(r[1]), "=r"(r[2]), "=r"(r[3]) : "r"(addr));
}
__device__ __forceinline__ void ldsm4t(uint32_t* r, uint32_t addr) {
    asm volatile("ldmatrix.sync.aligned.m8n8.x4.trans.shared.b16 {%0,%1,%2,%3}, [%4];"
                 : "=r"(r[0]), "=r"(r[1]), "=r"(r[2]), "=r"(r[3]) : "r"(addr));
}
__device__ __forceinline__ void mma16816(float* c, const uint32_t* a, const uint32_t* b) {
    asm volatile("mma.sync.aligned.m16n8k16.row.col.f32.f16.f16.f32 "
                 "{%0,%1,%2,%3}, {%4,%5,%6,%7}, {%8,%9}, {%0,%1,%2,%3};"
                 : "+f"(c[0]), "+f"(c[1]), "+f"(c[2]), "+f"(c[3])
                 : "r"(a[0]), "r"(a[1]), "r"(a[2]), "r"(a[3]), "r"(b[0]), "r"(b[1]));
}
__device__ __forceinline__ void cp16(uint32_t dst, const void* src) {
    asm volatile("cp.async.ca.shared.global [%0], [%1], 16;" :: "r"(dst), "l"(src));
}
__device__ __forceinline__ void cp_commit() {
    asm volatile("cp.async.commit_group;" ::: "memory");
}
__device__ __forceinline__ void cp_wait_all() {
    asm volatile("cp.async.wait_group 0;" ::: "memory");
}

// ---------------- adj helpers ----------------
__device__ __forceinline__ int load_adj(const void* adj, long long i, int is64) {
    if (is64) return (int)((const long long*)adj)[i];
    return ((const int*)adj)[i];
}

// ---------------- fused init: zero degrees + dtype detect ----------------
__global__ void init_kernel(const void* adj) {
    int i = blockIdx.x * blockDim.x + threadIdx.x;
    if (i < N_NODES) g_deg[i] = 0;
    if (i == 0) {
        const int* p = (const int*)adj;
        int acc = 0;
#pragma unroll
        for (int k = 0; k < 64; k++) acc |= p[2 * k + 1];
        for (int k = 0; k < 64; k++) acc |= p[2 * (k * 9973 + 1000) + 1];
        g_is64 = (acc == 0) ? 1 : 0;
    }
}

// ---------------- W fp16 prep ----------------
__global__ void wprep_kernel(const float* __restrict__ W) {
    int i = blockIdx.x * blockDim.x + threadIdx.x;
    if (i >= IN_F * HID) return;
    g_wfh[i] = __float2half_rn(W[i]);
}

// ---------------- pipelined fp16 HMMA GEMM, 2 CTAs/SM ----------------
__global__ void __launch_bounds__(256, 2) gemm_kernel(const float* __restrict__ A,
                                                      const float* __restrict__ attsrc,
                                                      const float* __restrict__ attdst) {
    extern __shared__ __half sm[];
    const int tid = threadIdx.x, lane = tid & 31, wid = tid >> 5;
    const int row0 = blockIdx.x * TILE_M;
    const int warp_m = wid & 3, warp_n = wid >> 2;

    float acc[16][4];
#pragma unroll
    for (int t = 0; t < 16; t++)
#pragma unroll
        for (int j = 0; j < 4; j++) acc[t][j] = 0.f;

    // A staging: thread -> (row = tid/2, 32-elem half = tid&1)
    const int ar = tid >> 1, ah_ = tid & 1;
    const int agr = row0 + ar;
    // W cp.async: 1024 16B-chunks per K-chunk; 4 per thread
    const int wc0 = (tid & 15) * 8;

    uint32_t h[16];

#define LOAD_A(c) do {                                                          \
        const int k0 = (c) * KC;                                                \
        if (agr < N_NODES) {                                                    \
            const float4* src = (const float4*)&A[(size_t)agr * IN_F + k0 + ah_ * 32]; \
            _Pragma("unroll")                                                   \
            for (int q = 0; q < 8; q++) {                                       \
                float4 v = src[q];                                              \
                __half2 p0 = __floats2half2_rn(v.x, v.y);                       \
                __half2 p1 = __floats2half2_rn(v.z, v.w);                       \
                h[2*q]   = *reinterpret_cast<uint32_t*>(&p0);                   \
                h[2*q+1] = *reinterpret_cast<uint32_t*>(&p1);                   \
            }                                                                   \
        } else {                                                                \
            _Pragma("unroll")                                                   \
            for (int q = 0; q < 16; q++) h[q] = 0u;                             \
        }                                                                       \
    } while (0)

#define STORE_A(b) do {                                                         \
        __half* ph = &(sm + (b) * BUFE)[ar * A_LD + ah_ * 32];                  \
        *(uint4*)(ph)      = make_uint4(h[0],  h[1],  h[2],  h[3]);             \
        *(uint4*)(ph + 8)  = make_uint4(h[4],  h[5],  h[6],  h[7]);             \
        *(uint4*)(ph + 16) = make_uint4(h[8],  h[9],  h[10], h[11]);            \
        *(uint4*)(ph + 24) = make_uint4(h[12], h[13], h[14], h[15]);            \
    } while (0)

#define ISSUE_W(c, b) do {                                                      \
        const int k0 = (c) * KC;                                                \
        uint32_t wh = smem_u32(sm + (b) * BUFE + ABUF);                         \
        _Pragma("unroll")                                                       \
        for (int j = 0; j < 4; j++) {                                           \
            int wrow = (tid + 256 * j) >> 4;                                    \
            cp16(wh + (wrow * W_LD + wc0) * 2,                                  \
                 &g_wfh[(size_t)(k0 + wrow) * HID + wc0]);                      \
        }                                                                       \
        cp_commit();                                                            \
    } while (0)

    ISSUE_W(0, 0);
    LOAD_A(0);
    STORE_A(0);
    cp_wait_all();
    __syncthreads();

    for (int c = 0; c < NCHUNK; c++) {
        const int buf = c & 1;
        if (c < NCHUNK - 1) {
            ISSUE_W(c + 1, buf ^ 1);
            LOAD_A(c + 1);          // LDGs + converts overlap the MMAs below
        }

        const __half* Ah = sm + buf * BUFE;
        const __half* Wh = Ah + ABUF;

#pragma unroll
        for (int ks = 0; ks < 4; ks++) {
            uint32_t a_h[2][4];
#pragma unroll
            for (int mi = 0; mi < 2; mi++) {
                uint32_t aoff = (warp_m * 32 + mi * 16 + (lane & 15)) * A_LD
                              + ks * 16 + (lane >> 4) * 8;
                ldsm4(a_h[mi], smem_u32(&Ah[aoff]));
            }
#pragma unroll
            for (int nt = 0; nt < 4; nt++) {
                uint32_t b_h[4];
                uint32_t woff = (ks * 16 + (lane & 15)) * W_LD
                              + warp_n * 64 + nt * 16 + (lane >> 4) * 8;
                ldsm4t(b_h, smem_u32(&Wh[woff]));
#pragma unroll
                for (int mi = 0; mi < 2; mi++) {
                    int t = mi * 8 + nt * 2;
                    mma16816(acc[t],     a_h[mi], b_h);
                    mma16816(acc[t + 1], a_h[mi], b_h + 2);
                }
            }
        }
        if (c < NCHUNK - 1) {
            STORE_A(buf ^ 1);
            cp_wait_all();
        }
        __syncthreads();
    }

    // ---- epilogue: fp16 g_xh + fused attention dots ----
    float sd[2][2] = {{0.f, 0.f}, {0.f, 0.f}};
    float dd[2][2] = {{0.f, 0.f}, {0.f, 0.f}};
#pragma unroll
    for (int mi = 0; mi < 2; mi++) {
        const int rlo = row0 + warp_m * 32 + mi * 16 + (lane >> 2);
        const int rhi = rlo + 8;
#pragma unroll
        for (int nt = 0; nt < 4; nt++) {
#pragma unroll
            for (int hh = 0; hh < 2; hh++) {
                int t = mi * 8 + nt * 2 + hh;
                int col = warp_n * 64 + nt * 16 + hh * 8 + (lane & 3) * 2;
                float as0 = __ldg(&attsrc[col]), as1 = __ldg(&attsrc[col + 1]);
                float ad0 = __ldg(&attdst[col]), ad1 = __ldg(&attdst[col + 1]);
                float2 v0 = make_float2(acc[t][0], acc[t][1]);
                float2 v1 = make_float2(acc[t][2], acc[t][3]);
                sd[mi][0] += v0.x * as0 + v0.y * as1;
                dd[mi][0] += v0.x * ad0 + v0.y * ad1;
                sd[mi][1] += v1.x * as0 + v1.y * as1;
                dd[mi][1] += v1.x * ad0 + v1.y * ad1;
                if (rlo < N_NODES) {
                    __half2 p = __float22half2_rn(v0);
                    *(uint32_t*)&g_xh[(size_t)rlo * HID + col] = *(uint32_t*)&p;
                }
                if (rhi < N_NODES) {
                    __half2 p = __float22half2_rn(v1);
                    *(uint32_t*)&g_xh[(size_t)rhi * HID + col] = *(uint32_t*)&p;
                }
            }
        }
    }
#pragma unroll
    for (int o = 1; o <= 2; o <<= 1) {
#pragma unroll
        for (int mi = 0; mi < 2; mi++)
#pragma unroll
            for (int hh = 0; hh < 2; hh++) {
                sd[mi][hh] += __shfl_xor_sync(0xffffffffu, sd[mi][hh], o);
                dd[mi][hh] += __shfl_xor_sync(0xffffffffu, dd[mi][hh], o);
            }
    }
    float* sdp = (float*)sm;
    float* ddp = sdp + 256;
    if ((lane & 3) == 0) {
#pragma unroll
        for (int mi = 0; mi < 2; mi++)
#pragma unroll
            for (int hh = 0; hh < 2; hh++) {
                int rt = warp_m * 32 + mi * 16 + (lane >> 2) + hh * 8;
                sdp[rt * 2 + warp_n] = sd[mi][hh];
                ddp[rt * 2 + warp_n] = dd[mi][hh];
            }
    }
    __syncthreads();
    if (tid < 128) {
        int gr = row0 + tid;
        if (gr < N_NODES) {
            g_asrc[gr] = sdp[tid * 2] + sdp[tid * 2 + 1];
            g_adst[gr] = ddp[tid * 2] + ddp[tid * 2 + 1];
        }
    }
}

// ---------------- histogram ----------------
__global__ void hist_kernel(const void* __restrict__ adj) {
    int i = blockIdx.x * blockDim.x + threadIdx.x;
    if (i >= TOT_E) return;
    int is64 = g_is64;
    int d = (i < N_EDGES) ? load_adj(adj, (long long)N_EDGES + i, is64) : (i - N_EDGES);
    atomicAdd(&g_deg[d], 1);
}

// ---------------- device-wide scan ----------------
__global__ void __launch_bounds__(1024) scan1_kernel() {
    __shared__ int ws[32];
    int tid = threadIdx.x, lane = tid & 31, wid = tid >> 5;
    int i = blockIdx.x * 1024 + tid;
    int v = (i < N_NODES) ? g_deg[i] : 0;
#pragma unroll
    for (int o = 16; o; o >>= 1) v += __shfl_down_sync(0xffffffffu, v, o);
    if (lane == 0) ws[wid] = v;
    __syncthreads();
    if (wid == 0) {
        int s = ws[lane];
#pragma unroll
        for (int o = 16; o; o >>= 1) s += __shfl_down_sync(0xffffffffu, s, o);
        if (lane == 0) g_part[blockIdx.x] = s;
    }
}
__global__ void scan2_kernel() {
    __shared__ int ws[4];
    int tid = threadIdx.x, lane = tid & 31, wid = tid >> 5;
    int v = (tid < NBLK_SCAN) ? g_part[tid] : 0;
    int incl = v;
#pragma unroll
    for (int o = 1; o < 32; o <<= 1) {
        int t = __shfl_up_sync(0xffffffffu, incl, o);
        if (lane >= o) incl += t;
    }
    if (lane == 31) ws[wid] = incl;
    __syncthreads();
    int base = 0;
    for (int w = 0; w < wid; w++) base += ws[w];
    if (tid < NBLK_SCAN) g_part[tid] = base + incl - v;
    if (tid == 127) g_off[N_NODES] = base + incl;
}
__global__ void __launch_bounds__(1024) scan3_kernel() {
    __shared__ int ws[32];
    int tid = threadIdx.x, lane = tid & 31, wid = tid >> 5;
    int i = blockIdx.x * 1024 + tid;
    int v = (i < N_NODES) ? g_deg[i] : 0;
    int incl = v;
#pragma unroll
    for (int o = 1; o < 32; o <<= 1) {
        int t = __shfl_up_sync(0xffffffffu, incl, o);
        if (lane >= o) incl += t;
    }
    if (lane == 31) ws[wid] = incl;
    __syncthreads();
    if (wid == 0) {
        int s = ws[lane];
        int sc = s;
#pragma unroll
        for (int o = 1; o < 32; o <<= 1) {
            int t = __shfl_up_sync(0xffffffffu, sc, o);
            if (lane >= o) sc += t;
        }
        ws[lane] = sc - s;
    }
    __syncthreads();
    int excl = g_part[blockIdx.x] + ws[wid] + incl - v;
    if (i < N_NODES) { g_off[i] = excl; g_cur[i] = excl; }
}

// ---------------- scatter (packed int2 writes) ----------------
__global__ void scatter_kernel(const void* __restrict__ adj) {
    int i = blockIdx.x * blockDim.x + threadIdx.x;
    if (i >= TOT_E) return;
    int is64 = g_is64;
    int s, d;
    if (i < N_EDGES) {
        s = load_adj(adj, i, is64);
        d = load_adj(adj, (long long)N_EDGES + i, is64);
    } else {
        s = i - N_EDGES;
        d = s;
    }
    float e = g_asrc[s] + g_adst[d];
    e = (e > 0.f) ? e : 0.2f * e;
    float ex = __expf(e);
    int pos = atomicAdd(&g_cur[d], 1);
    g_edge[pos] = make_int2(s, __float_as_int(ex));
}

// ---------------- aggregation (fp16 gather, packed edge reads) ----------------
__global__ void agg_kernel(const float* __restrict__ bias, float* __restrict__ out) {
    int w = (blockIdx.x * blockDim.x + threadIdx.x) >> 5;
    int lane = threadIdx.x & 31;
    if (w >= N_NODES) return;
    int st = g_off[w], en = g_off[w + 1];
    float4 acc = make_float4(0.f, 0.f, 0.f, 0.f);
    float ssum = 0.f;
    for (int j = st; j < en; j++) {
        int2 se = g_edge[j];
        float ex = __int_as_float(se.y);
        uint2 raw = *(const uint2*)&g_xh[(size_t)se.x * HID + lane * 4];
        __half2 p0 = *reinterpret_cast<__half2*>(&raw.x);
        __half2 p1 = *reinterpret_cast<__half2*>(&raw.y);
        float2 f0 = __half22float2(p0);
        float2 f1 = __half22float2(p1);
        ssum += ex;
        acc.x += ex * f0.x;
        acc.y += ex * f0.y;
        acc.z += ex * f1.x;
        acc.w += ex * f1.y;
    }
    float inv = 1.f / (ssum + 1e-16f);
    float4 b = *(const float4*)&bias[lane * 4];
    float4 o;
    o.x = acc.x * inv + b.x;
    o.y = acc.y * inv + b.y;
    o.z = acc.z * inv + b.z;
    o.w = acc.w * inv + b.w;
    o.x = (o.x > 0.f) ? o.x : 0.25f * o.x;
    o.y = (o.y > 0.f) ? o.y : 0.25f * o.y;
    o.z = (o.z > 0.f) ? o.z : 0.25f * o.z;
    o.w = (o.w > 0.f) ? o.w : 0.25f * o.w;
    *(float4*)&out[(size_t)w * HID + lane * 4] = o;
}

// ---------------- launcher ----------------
extern "C" void kernel_launch(void* const* d_in, const int* in_sizes, int n_in,
                              void* d_out, int out_size) {
    const float* data   = (const float*)d_in[0];
    const void*  adj    = (const void*)d_in[1];
    const float* W      = (const float*)d_in[2];
    const float* attsrc = (const float*)d_in[3];
    const float* attdst = (const float*)d_in[4];
    const float* bias   = (const float*)d_in[5];
    float* out = (float*)d_out;

    cudaFuncSetAttribute(gemm_kernel, cudaFuncAttributeMaxDynamicSharedMemorySize, S_BYTES);

    init_kernel<<<(N_NODES + 255) / 256, 256>>>(adj);
    wprep_kernel<<<(IN_F * HID + 255) / 256, 256>>>(W);
    gemm_kernel<<<(N_NODES + TILE_M - 1) / TILE_M, 256, S_BYTES>>>(data, attsrc, attdst);
    hist_kernel<<<(TOT_E + 255) / 256, 256>>>(adj);
    scan1_kernel<<<NBLK_SCAN, 1024>>>();
    scan2_kernel<<<1, 128>>>();
    scan3_kernel<<<NBLK_SCAN, 1024>>>();
    scatter_kernel<<<(TOT_E + 255) / 256, 256>>>(adj);
    agg_kernel<<<(N_NODES * 32 + 255) / 256, 256>>>(bias, out);
}